// round 12
// baseline (speedup 1.0000x reference)
#include <cuda_runtime.h>
#include <math.h>
#include <stdint.h>

// ---------------------------------------------------------------------------
// DeBERTa layer. tf32 mma.sync GEMMs (3-stage cp.async) + fused
// flash-attention middle (c2c + c2p/p2c gather + online softmax + P@V in one
// kernel; no score/prob tensors ever hit DRAM).
// B=16 S=512 H=768 NH=12 DH=64 P=512 I=3072.
// scores[i,j] = q_i.k_j + q_i.PK[i-j+P] + k_j.PQ[j-i+P]  (no clip: |i-j|<=511)
// ---------------------------------------------------------------------------

constexpr int kB  = 16;
constexpr int kS  = 512;
constexpr int kH  = 768;
constexpr int kNH = 12;
constexpr int kDH = 64;
constexpr int kP  = 512;
constexpr int kI  = 3072;
constexpr int kBS = kB * kS;    // 8192
constexpr int kBH = kB * kNH;   // 192
constexpr float kScale = 0.07216878364870322f;  // 1/sqrt(3*64)

constexpr size_t NOBIAS = (size_t)-1;

// ---- scratch layout ----
constexpr size_t SZ_QKV = (size_t)kBH * kS * kDH;
constexpr size_t SZ_POS = (size_t)kNH * 2 * kP * kDH;
constexpr size_t SZ_CP  = (size_t)kBH * kS * 2 * kP;
constexpr size_t SZ_W   = (size_t)kH * kH;
constexpr size_t SZ_W1  = (size_t)kH * kI;

constexpr size_t OFF_Q    = 0;
constexpr size_t OFF_K    = OFF_Q + SZ_QKV;
constexpr size_t OFF_V    = OFF_K + SZ_QKV;
constexpr size_t OFF_PK   = OFF_V + SZ_QKV;
constexpr size_t OFF_PQ   = OFF_PK + SZ_POS;
constexpr size_t OFF_C2P  = OFF_PQ + SZ_POS;
constexpr size_t OFF_P2C  = OFF_C2P + SZ_CP;
constexpr size_t OFF_CTX  = OFF_P2C + SZ_CP;
constexpr size_t OFF_T1   = OFF_CTX + SZ_QKV;
constexpr size_t OFF_H1   = OFF_T1 + SZ_QKV;  // fp32 (residual path)
constexpr size_t OFF_H1R  = OFF_H1 + SZ_QKV;  // tf32-rounded (FFN1 A)
constexpr size_t OFF_F1   = OFF_C2P;          // alias: c2p dead after flash
constexpr size_t OFF_CHS  = OFF_H1R + SZ_QKV;
constexpr size_t OFF_CPE  = OFF_CHS + SZ_QKV;
constexpr size_t OFF_CWQ  = OFF_CPE + SZ_POS;
constexpr size_t OFF_CWK  = OFF_CWQ + SZ_W;
constexpr size_t OFF_CWV  = OFF_CWK + SZ_W;
constexpr size_t OFF_CWPK = OFF_CWV + SZ_W;
constexpr size_t OFF_CWPQ = OFF_CWPK + SZ_W;
constexpr size_t OFF_CWO  = OFF_CWPQ + SZ_W;
constexpr size_t OFF_CW1  = OFF_CWO + SZ_W;
constexpr size_t OFF_CW2  = OFF_CW1 + SZ_W1;
constexpr size_t OFF_CB   = OFF_CW2 + SZ_W1;
constexpr size_t TOTAL    = OFF_CB + 3 * kH;

__device__ __align__(256) float g_scratch[TOTAL];

enum { EPI_NONE = 0, EPI_GELU = 1, EPI_QKV = 2, EPI_POS = 3 };

__device__ __forceinline__ uint32_t cvt_tf32(float x) {
    uint32_t u;
    asm("cvt.rna.tf32.f32 %0, %1;" : "=r"(u) : "f"(x));
    return u;
}
__device__ __forceinline__ float rnd_tf32(float x) {
    return __uint_as_float(cvt_tf32(x));
}

__device__ __forceinline__ void mma_tf32(float (&d)[4], const uint32_t (&a)[4],
                                         const uint32_t (&b)[2]) {
    asm volatile(
        "mma.sync.aligned.m16n8k8.row.col.f32.tf32.tf32.f32 "
        "{%0,%1,%2,%3}, {%4,%5,%6,%7}, {%8,%9}, {%0,%1,%2,%3};"
        : "+f"(d[0]), "+f"(d[1]), "+f"(d[2]), "+f"(d[3])
        : "r"(a[0]), "r"(a[1]), "r"(a[2]), "r"(a[3]), "r"(b[0]), "r"(b[1]));
}

__device__ __forceinline__ void cp_async16(uint32_t smem, const void* g) {
    asm volatile("cp.async.cg.shared.global [%0], [%1], 16;" :: "r"(smem), "l"(g));
}
__device__ __forceinline__ void cp_commit() {
    asm volatile("cp.async.commit_group;" ::: "memory");
}
__device__ __forceinline__ void cp_wait1() {
    asm volatile("cp.async.wait_group 1;" ::: "memory");
}

// ---------------------------------------------------------------------------
// Pre-round external GEMM operands to tf32 (RNA) into scratch.
// ---------------------------------------------------------------------------
constexpr size_t F4_HS = SZ_QKV / 4;
constexpr size_t F4_PE = SZ_POS / 4;
constexpr size_t F4_W  = SZ_W / 4;
constexpr size_t F4_W1 = SZ_W1 / 4;
constexpr size_t F4_TOTAL = F4_HS + F4_PE + 6 * F4_W + 2 * F4_W1;

__global__ __launch_bounds__(256)
void preconvert_kernel(const float* __restrict__ hs, const float* __restrict__ pe,
                       const float* __restrict__ Wq, const float* __restrict__ Wk,
                       const float* __restrict__ Wv, const float* __restrict__ Wpk,
                       const float* __restrict__ Wpq, const float* __restrict__ Wo,
                       const float* __restrict__ W1, const float* __restrict__ W2,
                       const float* __restrict__ bq, const float* __restrict__ bk,
                       const float* __restrict__ bv)
{
    size_t i = (size_t)blockIdx.x * 256 + threadIdx.x;
    if (i < 576) {
        float4* cb = reinterpret_cast<float4*>(g_scratch + OFF_CB);
        if (i < 192)      cb[i] = reinterpret_cast<const float4*>(bq)[i];
        else if (i < 384) cb[i] = reinterpret_cast<const float4*>(bk)[i - 192];
        else              cb[i] = reinterpret_cast<const float4*>(bv)[i - 384];
    }
    const float* src; float* dst;
    if (i < F4_HS)                 { src = hs;  dst = g_scratch + OFF_CHS; }
    else if ((i -= F4_HS) < F4_PE) { src = pe;  dst = g_scratch + OFF_CPE; }
    else if ((i -= F4_PE) < F4_W)  { src = Wq;  dst = g_scratch + OFF_CWQ; }
    else if ((i -= F4_W) < F4_W)   { src = Wk;  dst = g_scratch + OFF_CWK; }
    else if ((i -= F4_W) < F4_W)   { src = Wv;  dst = g_scratch + OFF_CWV; }
    else if ((i -= F4_W) < F4_W)   { src = Wpk; dst = g_scratch + OFF_CWPK; }
    else if ((i -= F4_W) < F4_W)   { src = Wpq; dst = g_scratch + OFF_CWPQ; }
    else if ((i -= F4_W) < F4_W)   { src = Wo;  dst = g_scratch + OFF_CWO; }
    else if ((i -= F4_W) < F4_W1)  { src = W1;  dst = g_scratch + OFF_CW1; }
    else { i -= F4_W1;               src = W2;  dst = g_scratch + OFF_CW2; }
    float4 v = reinterpret_cast<const float4*>(src)[i];
    v.x = rnd_tf32(v.x); v.y = rnd_tf32(v.y);
    v.z = rnd_tf32(v.z); v.w = rnd_tf32(v.w);
    reinterpret_cast<float4*>(dst)[i] = v;
}

// ---------------------------------------------------------------------------
// Pipelined tensor-core GEMM (unchanged from R10, minus score/ctx epilogues).
// ---------------------------------------------------------------------------
template<int BM, int BN, int BK, int WM, int WN, bool TB, bool DIAG, int EPI, bool RND>
__global__ __launch_bounds__(256, 2)
void gemm_tc(const float* __restrict__ Aex, size_t aOff,
             const float* __restrict__ Bex, size_t bOff,
             const float* __restrict__ biasEx, size_t biasOff, size_t biasStride,
             float* __restrict__ Cex, size_t cOff,
             int M, int N, int K,
             size_t aStride, size_t bStride, int bMod, size_t cStride)
{
    static_assert(WM * WN * 32 == 256, "");
    constexpr int WTM = BM / WM;
    constexpr int WTN = BN / WN;
    constexpr int MT  = WTM / 16;
    constexpr int NT  = WTN / 8;
    constexpr int ASTR  = BK + 4;
    constexpr int BSTR  = TB ? (BK + 4) : (BN + 8);
    constexpr int BROWS = TB ? BN : BK;
    constexpr int ASTAGE = BM * ASTR;
    constexpr int BSTAGE = BROWS * BSTR;
    constexpr int LA = (BM * BK) / (4 * 256);
    constexpr int LB = TB ? (BN * BK) / (4 * 256) : (BK * BN) / (4 * 256);

    extern __shared__ __align__(16) float dsm[];
    float* As = dsm;
    float* Bs = dsm + 3 * ASTAGE;

    const float* A  = Aex ? Aex : (const float*)g_scratch + aOff;
    const float* Bp = Bex ? Bex : (const float*)g_scratch + bOff;
    float*       C  = Cex ? Cex : g_scratch + cOff;
    const float* bias = biasEx ? biasEx
                      : (biasOff != NOBIAS ? (const float*)g_scratch + biasOff
                                           : nullptr);

    const int z = blockIdx.z;
    A  += (size_t)z * aStride;
    Bp += (size_t)(z % bMod) * bStride;

    const int m0 = blockIdx.y * BM;
    const int n0 = DIAG ? (blockIdx.y * BM + blockIdx.x * BN) : (blockIdx.x * BN);
    const int tid  = threadIdx.x;
    const int warp = tid >> 5;
    const int lane = tid & 31;
    const int wm = warp % WM, wn = warp / WM;
    const int mBase = wm * WTM, nBase = wn * WTN;
    const int gi = lane >> 2, gj = lane & 3;

    const uint32_t sAs = (uint32_t)__cvta_generic_to_shared(As);
    const uint32_t sBs = (uint32_t)__cvta_generic_to_shared(Bs);

    const int aRow = tid >> 3, aKg = tid & 7;
    const int bKr = TB ? 0 : (tid / (BN / 4));
    const int bNg = TB ? 0 : (tid % (BN / 4));

    auto load_stage = [&](int stage, int kblk) {
#pragma unroll
        for (int r = 0; r < LA; r++) {
            const int row = aRow + r * 32;
            cp_async16(sAs + (uint32_t)(stage * ASTAGE + row * ASTR + aKg * 4) * 4,
                       A + (size_t)(m0 + row) * K + kblk + aKg * 4);
        }
        if constexpr (TB) {
#pragma unroll
            for (int r = 0; r < LB; r++) {
                const int row = aRow + r * 32;
                cp_async16(sBs + (uint32_t)(stage * BSTAGE + row * BSTR + aKg * 4) * 4,
                           Bp + (size_t)(n0 + row) * K + kblk + aKg * 4);
            }
        } else {
#pragma unroll
            for (int r = 0; r < LB; r++) {
                const int kr = bKr + r * (1024 / BN);
                cp_async16(sBs + (uint32_t)(stage * BSTAGE + kr * BSTR + bNg * 4) * 4,
                           Bp + (size_t)(kblk + kr) * N + n0 + bNg * 4);
            }
        }
    };

    float acc[MT][NT][4];
#pragma unroll
    for (int i = 0; i < MT; i++)
#pragma unroll
        for (int j = 0; j < NT; j++)
#pragma unroll
            for (int r = 0; r < 4; r++) acc[i][j][r] = 0.f;

    load_stage(0, 0);
    cp_commit();
    load_stage(1, BK);
    cp_commit();

    const int TSTEPS = K / BK;
    for (int t = 0; t < TSTEPS; t++) {
        cp_wait1();
        __syncthreads();
        if (t + 2 < TSTEPS) load_stage((t + 2) % 3, (t + 2) * BK);
        cp_commit();

        const int cur = t % 3;
        const uint32_t* Ac = reinterpret_cast<const uint32_t*>(As) + cur * ASTAGE;
        const uint32_t* Bc = reinterpret_cast<const uint32_t*>(Bs) + cur * BSTAGE;
#pragma unroll
        for (int ks = 0; ks < BK / 8; ks++) {
            const int kk = ks * 8;
            uint32_t af[MT][4];
#pragma unroll
            for (int mt = 0; mt < MT; mt++) {
                const int r0 = (mBase + mt * 16 + gi) * ASTR + kk + gj;
                af[mt][0] = Ac[r0];
                af[mt][1] = Ac[r0 + 8 * ASTR];
                af[mt][2] = Ac[r0 + 4];
                af[mt][3] = Ac[r0 + 8 * ASTR + 4];
            }
            uint32_t bf[NT][2];
#pragma unroll
            for (int nt = 0; nt < NT; nt++) {
                const int col = nBase + nt * 8 + gi;
                if constexpr (TB) {
                    const int b0 = col * BSTR + kk + gj;
                    bf[nt][0] = Bc[b0];
                    bf[nt][1] = Bc[b0 + 4];
                } else {
                    const int b0 = (kk + gj) * BSTR + col;
                    bf[nt][0] = Bc[b0];
                    bf[nt][1] = Bc[b0 + 4 * BSTR];
                }
            }
#pragma unroll
            for (int mt = 0; mt < MT; mt++)
#pragma unroll
                for (int nt = 0; nt < NT; nt++)
                    mma_tf32(acc[mt][nt], af[mt], bf[nt]);
        }
    }

#pragma unroll
    for (int mt = 0; mt < MT; mt++) {
#pragma unroll
        for (int nt = 0; nt < NT; nt++) {
#pragma unroll
            for (int half = 0; half < 2; half++) {
                const int m = m0 + mBase + mt * 16 + gi + half * 8;
                const int n = n0 + nBase + nt * 8 + 2 * gj;
                float v0 = acc[mt][nt][half * 2 + 0];
                float v1 = acc[mt][nt][half * 2 + 1];
                if (bias) {
                    const float* bz = bias + (size_t)(z % bMod) * biasStride;
                    v0 += bz[n]; v1 += bz[n + 1];
                }
                if constexpr (EPI == EPI_GELU) {
                    v0 = 0.5f * v0 * (1.f + erff(v0 * 0.70710678118654752f));
                    v1 = 0.5f * v1 * (1.f + erff(v1 * 0.70710678118654752f));
                }
                if constexpr (RND) { v0 = rnd_tf32(v0); v1 = rnd_tf32(v1); }
                size_t o;
                if constexpr (EPI == EPI_QKV) {
                    const int bb = m >> 9, s = m & 511, h = n >> 6, d = n & 63;
                    o = ((size_t)(bb * kNH + h) * kS + s) * kDH + d
                      + (size_t)z * cStride;
                } else if constexpr (EPI == EPI_POS) {
                    const int h = n >> 6, d = n & 63;
                    o = ((size_t)h * (2 * kP) + m) * kDH + d
                      + (size_t)z * cStride;
                } else {
                    o = (size_t)z * cStride + (size_t)m * N + n;
                }
                *reinterpret_cast<float2*>(&C[o]) = make_float2(v0, v1);
            }
        }
    }
}

// ---------------------------------------------------------------------------
// Fused flash attention: per (z, 128-row i-tile):
//   loop j-tiles: S = Q@K^T + p2c + c2p (staged), scale+mask, online softmax,
//   ctx += P@V. Writes merged-head CTX (tf32-rounded). No score DRAM traffic.
// 8 warps x 16 rows each (row stats warp-local; quad shuffles only).
// smem: Qs[128][68] Ks[128][68] Vs[128][72] Ps[128][132] = 174080 B.
// ---------------------------------------------------------------------------
constexpr int FA_QS = 0;
constexpr int FA_KS = 128 * 68;
constexpr int FA_VS = FA_KS + 128 * 68;
constexpr int FA_PS = FA_VS + 128 * 72;
constexpr int FA_SMEM = (FA_PS + 128 * 132) * 4;   // 174080 bytes

__global__ __launch_bounds__(256, 1)
void flash_attn_kernel(const float* __restrict__ mask)
{
    extern __shared__ __align__(16) float sm[];
    float* Qs = sm + FA_QS;
    float* Ks = sm + FA_KS;
    float* Vs = sm + FA_VS;
    float* Ps = sm + FA_PS;

    const int z  = blockIdx.y;
    const int i0 = blockIdx.x * 128;
    const int tid  = threadIdx.x;
    const int warp = tid >> 5;
    const int lane = tid & 31;
    const int gi = lane >> 2, gj = lane & 3;
    const int mBase = warp * 16;

    const float* Qz = g_scratch + OFF_Q + (size_t)z * kS * kDH;
    const float* Kz = g_scratch + OFF_K + (size_t)z * kS * kDH;
    const float* Vz = g_scratch + OFF_V + (size_t)z * kS * kDH;
    const float* C2Pz = g_scratch + OFF_C2P + (size_t)z * kS * (2 * kP);
    const float* P2Cz = g_scratch + OFF_P2C + (size_t)z * kS * (2 * kP);
    const float* mrow = mask + (size_t)(z / kNH) * kS;

    // load Q tile once: 128 rows x 16 float4
#pragma unroll
    for (int r = 0; r < 8; r++) {
        const int idx = tid + r * 256;
        const int row = idx >> 4, f4 = idx & 15;
        *reinterpret_cast<float4*>(&Qs[row * 68 + f4 * 4]) =
            *reinterpret_cast<const float4*>(&Qz[(size_t)(i0 + row) * kDH + f4 * 4]);
    }

    float ctx[8][4];
#pragma unroll
    for (int n = 0; n < 8; n++)
#pragma unroll
        for (int c = 0; c < 4; c++) ctx[n][c] = 0.f;
    float rm[2] = {-1e30f, -1e30f};
    float rs[2] = {0.f, 0.f};

    for (int jt = 0; jt < 4; jt++) {
        const int j0 = jt * 128;
        __syncthreads();   // prior iteration's smem reads complete
        // stage K, V tiles
#pragma unroll
        for (int r = 0; r < 8; r++) {
            const int idx = tid + r * 256;
            const int row = idx >> 4, f4 = idx & 15;
            *reinterpret_cast<float4*>(&Ks[row * 68 + f4 * 4]) =
                *reinterpret_cast<const float4*>(&Kz[(size_t)(j0 + row) * kDH + f4 * 4]);
            *reinterpret_cast<float4*>(&Vs[row * 72 + f4 * 4]) =
                *reinterpret_cast<const float4*>(&Vz[(size_t)(j0 + row) * kDH + f4 * 4]);
        }
        __syncthreads();

        // ---- S = Q @ K^T : warp tile 16x128, MT=1, NT=16 ----
        float accS[16][4];
#pragma unroll
        for (int n = 0; n < 16; n++)
#pragma unroll
            for (int c = 0; c < 4; c++) accS[n][c] = 0.f;
        const uint32_t* Qu = reinterpret_cast<const uint32_t*>(Qs);
        const uint32_t* Ku = reinterpret_cast<const uint32_t*>(Ks);
#pragma unroll
        for (int ks = 0; ks < 8; ks++) {
            const int kk = ks * 8;
            uint32_t af[4];
            const int r0 = (mBase + gi) * 68 + kk + gj;
            af[0] = Qu[r0];
            af[1] = Qu[r0 + 8 * 68];
            af[2] = Qu[r0 + 4];
            af[3] = Qu[r0 + 8 * 68 + 4];
#pragma unroll
            for (int nt = 0; nt < 16; nt++) {
                uint32_t bf[2];
                const int b0 = (nt * 8 + gi) * 68 + kk + gj;
                bf[0] = Ku[b0];
                bf[1] = Ku[b0 + 4];
                mma_tf32(accS[nt], af, bf);
            }
        }

        // ---- stage p2c tile: Ps[jl*132+il] = p2c_all[j0+jl][(j0+jl)-(i0+il)+P]
#pragma unroll
        for (int r = 0; r < 64; r++) {
            const int idx = tid + r * 256;
            const int jl = idx >> 7, il = idx & 127;
            Ps[jl * 132 + il] =
                P2Cz[(size_t)(j0 + jl) * (2 * kP) + (j0 + jl) - (i0 + il) + kP];
        }
        __syncthreads();
#pragma unroll
        for (int nt = 0; nt < 16; nt++)
#pragma unroll
            for (int half = 0; half < 2; half++) {
                const int il = mBase + gi + half * 8;
                const int jl = nt * 8 + 2 * gj;
                accS[nt][half * 2 + 0] += Ps[jl * 132 + il];
                accS[nt][half * 2 + 1] += Ps[(jl + 1) * 132 + il];
            }
        __syncthreads();
        // ---- stage c2p tile: Ps[il*132+jl] = c2p_all[i0+il][(i0+il)-(j0+jl)+P]
#pragma unroll
        for (int r = 0; r < 64; r++) {
            const int idx = tid + r * 256;
            const int il = idx >> 7, jl = idx & 127;
            Ps[il * 132 + jl] =
                C2Pz[(size_t)(i0 + il) * (2 * kP) + (i0 + il) - (j0 + jl) + kP];
        }
        __syncthreads();
        // ---- add c2p, scale, mask ----
#pragma unroll
        for (int nt = 0; nt < 16; nt++)
#pragma unroll
            for (int half = 0; half < 2; half++) {
                const int il = mBase + gi + half * 8;
                const int jl = nt * 8 + 2 * gj;
                float s0 = (accS[nt][half * 2 + 0] + Ps[il * 132 + jl]) * kScale;
                float s1 = (accS[nt][half * 2 + 1] + Ps[il * 132 + jl + 1]) * kScale;
                if (mrow[j0 + jl] <= 0.f)     s0 = -1e9f;
                if (mrow[j0 + jl + 1] <= 0.f) s1 = -1e9f;
                accS[nt][half * 2 + 0] = s0;
                accS[nt][half * 2 + 1] = s1;
            }

        // ---- online softmax update (rows warp-local; quad shuffles) ----
#pragma unroll
        for (int half = 0; half < 2; half++) {
            float tmax = -1e30f;
#pragma unroll
            for (int nt = 0; nt < 16; nt++)
                tmax = fmaxf(tmax, fmaxf(accS[nt][half * 2], accS[nt][half * 2 + 1]));
            tmax = fmaxf(tmax, __shfl_xor_sync(0xFFFFFFFFu, tmax, 1));
            tmax = fmaxf(tmax, __shfl_xor_sync(0xFFFFFFFFu, tmax, 2));
            const float mNew = fmaxf(rm[half], tmax);
            const float alpha = __expf(rm[half] - mNew);
            float lsum = 0.f;
#pragma unroll
            for (int nt = 0; nt < 16; nt++) {
                const float e0 = __expf(accS[nt][half * 2 + 0] - mNew);
                const float e1 = __expf(accS[nt][half * 2 + 1] - mNew);
                accS[nt][half * 2 + 0] = e0;
                accS[nt][half * 2 + 1] = e1;
                lsum += e0 + e1;
            }
            lsum += __shfl_xor_sync(0xFFFFFFFFu, lsum, 1);
            lsum += __shfl_xor_sync(0xFFFFFFFFu, lsum, 2);
            rs[half] = rs[half] * alpha + lsum;
            rm[half] = mNew;
#pragma unroll
            for (int n = 0; n < 8; n++) {
                ctx[n][half * 2 + 0] *= alpha;
                ctx[n][half * 2 + 1] *= alpha;
            }
        }

        __syncthreads();   // c2p reads done before P overwrite
        // ---- write P (tf32-rounded) m-major for a-fragment reload ----
#pragma unroll
        for (int nt = 0; nt < 16; nt++)
#pragma unroll
            for (int half = 0; half < 2; half++) {
                const int il = mBase + gi + half * 8;
                const int jl = nt * 8 + 2 * gj;
                *reinterpret_cast<float2*>(&Ps[il * 132 + jl]) =
                    make_float2(rnd_tf32(accS[nt][half * 2 + 0]),
                                rnd_tf32(accS[nt][half * 2 + 1]));
            }
        __syncthreads();

        // ---- ctx += P @ V : warp tile 16x64, k=128 ----
        const uint32_t* Pu = reinterpret_cast<const uint32_t*>(Ps);
        const uint32_t* Vu = reinterpret_cast<const uint32_t*>(Vs);
#pragma unroll
        for (int ks = 0; ks < 16; ks++) {
            const int kk = ks * 8;
            uint32_t af[4];
            const int r0 = (mBase + gi) * 132 + kk + gj;
            af[0] = Pu[r0];
            af[1] = Pu[r0 + 8 * 132];
            af[2] = Pu[r0 + 4];
            af[3] = Pu[r0 + 8 * 132 + 4];
#pragma unroll
            for (int nt = 0; nt < 8; nt++) {
                uint32_t bf[2];
                const int b0 = (kk + gj) * 72 + nt * 8 + gi;
                bf[0] = Vu[b0];
                bf[1] = Vu[b0 + 4 * 72];
                mma_tf32(ctx[nt], af, bf);
            }
        }
    }

    // ---- finalize: ctx /= sum; write merged-head [B,S,H], tf32-rounded ----
    const int bb = z / kNH, h = z % kNH;
    const float inv0 = 1.f / rs[0], inv1 = 1.f / rs[1];
    float* Cg = g_scratch + OFF_CTX;
#pragma unroll
    for (int nt = 0; nt < 8; nt++)
#pragma unroll
        for (int half = 0; half < 2; half++) {
            const int m = i0 + mBase + gi + half * 8;
            const int d = nt * 8 + 2 * gj;
            const float inv = half ? inv1 : inv0;
            const float v0 = rnd_tf32(ctx[nt][half * 2 + 0] * inv);
            const float v1 = rnd_tf32(ctx[nt][half * 2 + 1] * inv);
            *reinterpret_cast<float2*>(
                &Cg[((size_t)bb * kS + m) * kH + h * kDH + d]) =
                make_float2(v0, v1);
        }
}

// ---------------------------------------------------------------------------
// out = LayerNorm(X + Y) * g + b; optional tf32-rounded extra copy.
// ---------------------------------------------------------------------------
__global__ void add_ln_kernel(const float* __restrict__ Xex, size_t xOff, size_t yOff,
                              const float* __restrict__ g, const float* __restrict__ bb,
                              float* __restrict__ outEx, size_t outOff,
                              int makeRounded, size_t rOff)
{
    const float* X = Xex ? Xex : (const float*)g_scratch + xOff;
    const float* Y = (const float*)g_scratch + yOff;
    float* O = outEx ? outEx : g_scratch + outOff;

    const size_t off = (size_t)blockIdx.x * kH;
    const int t = threadIdx.x;
    const float v0 = X[off + t]       + Y[off + t];
    const float v1 = X[off + t + 256] + Y[off + t + 256];
    const float v2 = X[off + t + 512] + Y[off + t + 512];

    __shared__ float red[256];
    red[t] = v0 + v1 + v2;
    __syncthreads();
    for (int s = 128; s > 0; s >>= 1) {
        if (t < s) red[t] += red[t + s];
        __syncthreads();
    }
    const float mean = red[0] * (1.f / 768.f);
    __syncthreads();

    const float d0 = v0 - mean, d1 = v1 - mean, d2 = v2 - mean;
    red[t] = d0 * d0 + d1 * d1 + d2 * d2;
    __syncthreads();
    for (int s = 128; s > 0; s >>= 1) {
        if (t < s) red[t] += red[t + s];
        __syncthreads();
    }
    const float rstd = rsqrtf(red[0] * (1.f / 768.f) + 1e-7f);

    const float o0 = d0 * rstd * g[t]       + bb[t];
    const float o1 = d1 * rstd * g[t + 256] + bb[t + 256];
    const float o2 = d2 * rstd * g[t + 512] + bb[t + 512];
    O[off + t]       = o0;
    O[off + t + 256] = o1;
    O[off + t + 512] = o2;
    if (makeRounded) {
        float* R = g_scratch + rOff;
        R[off + t]       = rnd_tf32(o0);
        R[off + t + 256] = rnd_tf32(o1);
        R[off + t + 512] = rnd_tf32(o2);
    }
}

// ---------------------------------------------------------------------------
constexpr int SM_NN128 = 107520;
constexpr int SM_TB128 = 110592;

extern "C" void kernel_launch(void* const* d_in, const int* in_sizes, int n_in,
                              void* d_out, int out_size)
{
    const float* hs  = (const float*)d_in[0];
    const float* am  = (const float*)d_in[1];
    const float* pe  = (const float*)d_in[2];
    const float* Wq  = (const float*)d_in[3];
    const float* bq  = (const float*)d_in[4];
    const float* Wk  = (const float*)d_in[5];
    const float* bk  = (const float*)d_in[6];
    const float* Wv  = (const float*)d_in[7];
    const float* bv  = (const float*)d_in[8];
    const float* Wpk = (const float*)d_in[9];
    const float* Wpq = (const float*)d_in[10];
    const float* Wo  = (const float*)d_in[11];
    const float* bo  = (const float*)d_in[12];
    const float* g1  = (const float*)d_in[13];
    const float* be1 = (const float*)d_in[14];
    const float* W1  = (const float*)d_in[15];
    const float* b1  = (const float*)d_in[16];
    const float* W2  = (const float*)d_in[17];
    const float* b2  = (const float*)d_in[18];
    const float* g2  = (const float*)d_in[19];
    const float* be2 = (const float*)d_in[20];
    float* out = (float*)d_out;

    auto qkvK  = gemm_tc<128,128,32,4,2,false,false,EPI_QKV,true>;
    auto posK  = gemm_tc<128,128,32,4,2,false,false,EPI_POS,true>;
    auto bandK = gemm_tc<128,128,32,4,2,true,true,EPI_NONE,false>;
    auto nnK   = gemm_tc<128,128,32,4,2,false,false,EPI_NONE,false>;
    auto gelK  = gemm_tc<128,128,32,4,2,false,false,EPI_GELU,true>;
    cudaFuncSetAttribute((const void*)qkvK,  cudaFuncAttributeMaxDynamicSharedMemorySize, SM_NN128);
    cudaFuncSetAttribute((const void*)posK,  cudaFuncAttributeMaxDynamicSharedMemorySize, SM_NN128);
    cudaFuncSetAttribute((const void*)bandK, cudaFuncAttributeMaxDynamicSharedMemorySize, SM_TB128);
    cudaFuncSetAttribute((const void*)nnK,   cudaFuncAttributeMaxDynamicSharedMemorySize, SM_NN128);
    cudaFuncSetAttribute((const void*)gelK,  cudaFuncAttributeMaxDynamicSharedMemorySize, SM_NN128);
    cudaFuncSetAttribute((const void*)flash_attn_kernel,
                         cudaFuncAttributeMaxDynamicSharedMemorySize, FA_SMEM);

    // --- pre-round all external GEMM operands to tf32 ---
    preconvert_kernel<<<(int)(F4_TOTAL / 256), 256>>>(
        hs, pe, Wq, Wk, Wv, Wpk, Wpq, Wo, W1, W2, bq, bk, bv);

    // --- merged QKV (z selects weight/bias/output region) ---
    qkvK<<<dim3(kH/128, kBS/128, 3), 256, SM_NN128>>>(
        nullptr, OFF_CHS, nullptr, OFF_CWQ, nullptr, OFF_CB, kH,
        nullptr, OFF_Q, kBS, kH, kH, 0, SZ_W, 3, SZ_QKV);

    // --- merged position projections (z: PK/PQ) ---
    posK<<<dim3(kH/128, (2*kP)/128, 2), 256, SM_NN128>>>(
        nullptr, OFF_CPE, nullptr, OFF_CWPK, nullptr, NOBIAS, 0,
        nullptr, OFF_PK, 2*kP, kH, kH, 0, SZ_W, 2, SZ_POS);

    // --- c2p_all / p2c_all bands (diagonal tiles only) ---
    bandK<<<dim3(5, kS/128, kBH), 256, SM_TB128>>>(
        nullptr, OFF_Q, nullptr, OFF_PK, nullptr, NOBIAS, 0,
        nullptr, OFF_C2P, kS, 2*kP, kDH,
        (size_t)kS*kDH, (size_t)(2*kP)*kDH, kNH, (size_t)kS*(2*kP));
    bandK<<<dim3(5, kS/128, kBH), 256, SM_TB128>>>(
        nullptr, OFF_K, nullptr, OFF_PQ, nullptr, NOBIAS, 0,
        nullptr, OFF_P2C, kS, 2*kP, kDH,
        (size_t)kS*kDH, (size_t)(2*kP)*kDH, kNH, (size_t)kS*(2*kP));

    // --- fused flash attention: scores+softmax+P@V, writes CTX ---
    flash_attn_kernel<<<dim3(kS/128, kBH), 256, FA_SMEM>>>(am);

    // --- output projection + residual LN1 (H1 fp32 + tf32 copy) ---
    nnK<<<dim3(kH/128, kBS/128, 1), 256, SM_NN128>>>(
        nullptr, OFF_CTX, nullptr, OFF_CWO, bo, NOBIAS, 0,
        nullptr, OFF_T1, kBS, kH, kH, 0, 0, 1, 0);
    add_ln_kernel<<<kBS, 256>>>(hs, 0, OFF_T1, g1, be1, nullptr, OFF_H1, 1, OFF_H1R);

    // --- FFN ---
    gelK<<<dim3(kI/128, kBS/128, 1), 256, SM_NN128>>>(
        nullptr, OFF_H1R, nullptr, OFF_CW1, b1, NOBIAS, 0,
        nullptr, OFF_F1, kBS, kI, kH, 0, 0, 1, 0);
    nnK<<<dim3(kH/128, kBS/128, 1), 256, SM_NN128>>>(
        nullptr, OFF_F1, nullptr, OFF_CW2, b2, NOBIAS, 0,
        nullptr, OFF_T1, kBS, kH, kI, 0, 0, 1, 0);
    add_ln_kernel<<<kBS, 256>>>(nullptr, OFF_H1, OFF_T1, g2, be2, out, 0, 0, 0);
}

// round 15
// speedup vs baseline: 1.3534x; 1.3534x over previous
#include <cuda_runtime.h>
#include <cuda_fp16.h>
#include <math.h>
#include <stdint.h>

// ---------------------------------------------------------------------------
// DeBERTa layer, fp16 mma.sync m16n8k16 everywhere (fp32 accumulate).
// fp16 normals = 11-bit significand = tf32 precision, 2x HMMA throughput.
// Uniform K-contiguous operand layout (A m-major, B n-major) -> all fragments
// are raw 32-bit smem words, zero conversions in inner loops.
// CONVENTION: scratch offsets are float units; all z-strides passed to
// gemm_h are HALF units (R14's float-unit strides were the correctness bug).
// B=16 S=512 H=768 NH=12 DH=64 P=512 I=3072.
// ---------------------------------------------------------------------------

constexpr int kB  = 16;
constexpr int kS  = 512;
constexpr int kH  = 768;
constexpr int kNH = 12;
constexpr int kDH = 64;
constexpr int kP  = 512;
constexpr int kI  = 3072;
constexpr int kBS = kB * kS;
constexpr int kBH = kB * kNH;
constexpr float kScale = 0.07216878364870322f;

constexpr size_t SZ_QKV = (size_t)kBH * kS * kDH;
constexpr size_t SZ_POS = (size_t)kNH * 2 * kP * kDH;
constexpr size_t SZ_CP  = (size_t)kBH * kS * 2 * kP;
constexpr size_t SZ_W   = (size_t)kH * kH;
constexpr size_t SZ_W1  = (size_t)kH * kI;

constexpr size_t OFF_Q    = 0;
constexpr size_t OFF_K    = OFF_Q + SZ_QKV;
constexpr size_t OFF_V    = OFF_K + SZ_QKV;          // V^T layout [z][d][s]
constexpr size_t OFF_PK   = OFF_V + SZ_QKV;
constexpr size_t OFF_PQ   = OFF_PK + SZ_POS;
constexpr size_t OFF_C2P  = OFF_PQ + SZ_POS;
constexpr size_t OFF_P2C  = OFF_C2P + SZ_CP;
constexpr size_t OFF_CTX  = OFF_P2C + SZ_CP;
constexpr size_t OFF_T1   = OFF_CTX + SZ_QKV;        // fp32
constexpr size_t OFF_H1   = OFF_T1 + SZ_QKV;         // fp32 residual
constexpr size_t OFF_H1R  = OFF_H1 + SZ_QKV;         // half (FFN1 A)
constexpr size_t OFF_F1   = OFF_C2P;                 // alias, half
constexpr size_t OFF_CHS  = OFF_H1R + SZ_QKV;        // half
constexpr size_t OFF_CPE  = OFF_CHS + SZ_QKV;        // half
constexpr size_t OFF_CWQ  = OFF_CPE + SZ_POS;        // WT [N][K] half
constexpr size_t OFF_CWK  = OFF_CWQ + SZ_W;
constexpr size_t OFF_CWV  = OFF_CWK + SZ_W;
constexpr size_t OFF_CWPK = OFF_CWV + SZ_W;
constexpr size_t OFF_CWPQ = OFF_CWPK + SZ_W;
constexpr size_t OFF_CWO  = OFF_CWPQ + SZ_W;
constexpr size_t OFF_CW1  = OFF_CWO + SZ_W;
constexpr size_t OFF_CW2  = OFF_CW1 + SZ_W1;
constexpr size_t OFF_CB   = OFF_CW2 + SZ_W1;         // fp32 biases
constexpr size_t TOTAL    = OFF_CB + 3 * kH;

__device__ __align__(256) float g_scratch[TOTAL];

enum { EPI_NONE = 0, EPI_GELU = 1, EPI_QKV = 2, EPI_POS = 3 };
constexpr size_t NOBIAS = (size_t)-1;

// fp16 mma m16n8k16, fp32 accum. Lane = 4*gi + gj.
//  a0=(row gi, k 2gj..+1) a1=(gi+8, same) a2=(gi, k+8) a3=(gi+8, k+8)
//  b0=(k 2gj..+1, col gi) b1=(k+8, col gi)  c: rows gi/gi+8, cols 2gj..+1
__device__ __forceinline__ void mma_f16(float (&d)[4], const uint32_t (&a)[4],
                                        const uint32_t (&b)[2]) {
    asm volatile(
        "mma.sync.aligned.m16n8k16.row.col.f32.f16.f16.f32 "
        "{%0,%1,%2,%3}, {%4,%5,%6,%7}, {%8,%9}, {%0,%1,%2,%3};"
        : "+f"(d[0]), "+f"(d[1]), "+f"(d[2]), "+f"(d[3])
        : "r"(a[0]), "r"(a[1]), "r"(a[2]), "r"(a[3]), "r"(b[0]), "r"(b[1]));
}
__device__ __forceinline__ void cp_async16(uint32_t s, const void* g) {
    asm volatile("cp.async.cg.shared.global [%0], [%1], 16;" :: "r"(s), "l"(g));
}
__device__ __forceinline__ void cp_commit() {
    asm volatile("cp.async.commit_group;" ::: "memory");
}
__device__ __forceinline__ void cp_wait1() {
    asm volatile("cp.async.wait_group 1;" ::: "memory");
}
__device__ __forceinline__ void cp_wait0() {
    asm volatile("cp.async.wait_group 0;" ::: "memory");
}
__device__ __forceinline__ uint32_t smem_u32(const void* p) {
    return (uint32_t)__cvta_generic_to_shared(p);
}

// ---------------------------------------------------------------------------
// preconvert: hs/pe -> half; biases contiguous fp32.
// ---------------------------------------------------------------------------
constexpr size_t F4_HS = SZ_QKV / 4;
constexpr size_t F4_PE = SZ_POS / 4;
constexpr size_t F4_TOTAL = F4_HS + F4_PE;

__global__ __launch_bounds__(256)
void preconvert_kernel(const float* __restrict__ hs, const float* __restrict__ pe,
                       const float* __restrict__ bq, const float* __restrict__ bk,
                       const float* __restrict__ bv)
{
    size_t i = (size_t)blockIdx.x * 256 + threadIdx.x;
    if (i < 576) {
        float4* cb = reinterpret_cast<float4*>(g_scratch + OFF_CB);
        if (i < 192)      cb[i] = reinterpret_cast<const float4*>(bq)[i];
        else if (i < 384) cb[i] = reinterpret_cast<const float4*>(bk)[i - 192];
        else              cb[i] = reinterpret_cast<const float4*>(bv)[i - 384];
    }
    if (i >= F4_TOTAL) return;
    const float* src; __half2* dst;
    if (i < F4_HS) { src = hs; dst = reinterpret_cast<__half2*>(g_scratch + OFF_CHS); }
    else { i -= F4_HS; src = pe; dst = reinterpret_cast<__half2*>(g_scratch + OFF_CPE); }
    const float4 v = reinterpret_cast<const float4*>(src)[i];
    dst[i * 2]     = __floats2half2_rn(v.x, v.y);
    dst[i * 2 + 1] = __floats2half2_rn(v.z, v.w);
}

// ---------------------------------------------------------------------------
// transpose weights W[K,N] -> WT[N,K] half. 8064 flat 32x32 tiles.
// ---------------------------------------------------------------------------
__global__ __launch_bounds__(256)
void transpose_kernel(const float* __restrict__ Wq, const float* __restrict__ Wk,
                      const float* __restrict__ Wv, const float* __restrict__ Wpk,
                      const float* __restrict__ Wpq, const float* __restrict__ Wo,
                      const float* __restrict__ W1, const float* __restrict__ W2)
{
    int bid = blockIdx.x;
    const float* src; __half* dst; int R, C, t;
    if (bid < 3456) {
        const float* ws[6] = {Wq, Wk, Wv, Wpk, Wpq, Wo};
        const size_t od[6] = {OFF_CWQ, OFF_CWK, OFF_CWV, OFF_CWPK, OFF_CWPQ, OFF_CWO};
        src = ws[bid / 576]; dst = reinterpret_cast<__half*>(g_scratch + od[bid / 576]);
        R = kH; C = kH; t = bid % 576;
    } else if (bid < 5760) {
        src = W1; dst = reinterpret_cast<__half*>(g_scratch + OFF_CW1);
        R = kH; C = kI; t = bid - 3456;
    } else {
        src = W2; dst = reinterpret_cast<__half*>(g_scratch + OFF_CW2);
        R = kI; C = kH; t = bid - 5760;
    }
    const int n0 = (t % (C / 32)) * 32, k0 = (t / (C / 32)) * 32;
    __shared__ float tl[32][33];
    const int tx = threadIdx.x & 31, ty = threadIdx.x >> 5;
#pragma unroll
    for (int r = ty; r < 32; r += 8)
        tl[r][tx] = src[(size_t)(k0 + r) * C + n0 + tx];
    __syncthreads();
#pragma unroll
    for (int r = ty; r < 32; r += 8)
        dst[(size_t)(n0 + r) * R + k0 + tx] = __float2half_rn(tl[tx][r]);
}

// ---------------------------------------------------------------------------
// Dense fp16 GEMM: C = epi(A[M,K] @ WT[N,K]^T (+bias)). 128x128 tile,
// BK=32 halves, 3-stage cp.async ring. 8 warps 4x2 (warp tile 32x64).
// bStride / cStride are in HALF units; biasStride in floats.
// ---------------------------------------------------------------------------
constexpr int GH_HW  = 20;
constexpr int GH_STG = 128 * GH_HW;
constexpr int GH_SMEM = 6 * GH_STG * 4;

template<int EPI>
__global__ __launch_bounds__(256, 2)
void gemm_h(size_t aOff, size_t bOff, size_t bStride,
            const float* __restrict__ biasEx, size_t biasOff, size_t biasStride,
            size_t cOff, size_t cStride, int K, int Ntot)
{
    extern __shared__ __align__(16) uint32_t dsm[];
    uint32_t* As = dsm;
    uint32_t* Bs = dsm + 3 * GH_STG;

    const int z = blockIdx.z;
    const int m0 = blockIdx.y * 128, n0 = blockIdx.x * 128;
    const int tid = threadIdx.x, warp = tid >> 5, lane = tid & 31;
    const int wm = warp & 3, wn = warp >> 2;
    const int mBase = wm * 32, nBase = wn * 64;
    const int gi = lane >> 2, gj = lane & 3;

    const __half* Ah = reinterpret_cast<const __half*>(g_scratch + aOff)
                     + (size_t)m0 * K;
    const __half* Bh = reinterpret_cast<const __half*>(g_scratch + bOff)
                     + (size_t)z * bStride + (size_t)n0 * K;
    const uint32_t sA = smem_u32(As), sB = smem_u32(Bs);

    auto load_stage = [&](int st, int kblk) {
#pragma unroll
        for (int i = 0; i < 2; i++) {
            const int idx = tid + i * 256;
            const int row = idx >> 2, g = idx & 3;
            cp_async16(sA + (uint32_t)(st * GH_STG + row * GH_HW + g * 4) * 4,
                       Ah + (size_t)row * K + kblk + g * 8);
            cp_async16(sB + (uint32_t)(st * GH_STG + row * GH_HW + g * 4) * 4,
                       Bh + (size_t)row * K + kblk + g * 8);
        }
    };

    float acc[2][8][4];
#pragma unroll
    for (int i = 0; i < 2; i++)
#pragma unroll
        for (int j = 0; j < 8; j++)
#pragma unroll
            for (int r = 0; r < 4; r++) acc[i][j][r] = 0.f;

    const int NC = K / 32;
    load_stage(0, 0);  cp_commit();
    load_stage(1, 32); cp_commit();

    for (int c = 0; c < NC; c++) {
        cp_wait1();
        __syncthreads();
        if (c + 2 < NC) load_stage((c + 2) % 3, (c + 2) * 32);
        cp_commit();
        const uint32_t* Ac = As + (c % 3) * GH_STG;
        const uint32_t* Bc = Bs + (c % 3) * GH_STG;
#pragma unroll
        for (int ks = 0; ks < 2; ks++) {
            const int kk = ks * 8;
            uint32_t af[2][4];
#pragma unroll
            for (int mt = 0; mt < 2; mt++) {
                const int r0 = (mBase + mt * 16 + gi) * GH_HW + kk + gj;
                af[mt][0] = Ac[r0];
                af[mt][1] = Ac[r0 + 8 * GH_HW];
                af[mt][2] = Ac[r0 + 4];
                af[mt][3] = Ac[r0 + 8 * GH_HW + 4];
            }
            uint32_t bf[8][2];
#pragma unroll
            for (int nt = 0; nt < 8; nt++) {
                const int b0 = (nBase + nt * 8 + gi) * GH_HW + kk + gj;
                bf[nt][0] = Bc[b0];
                bf[nt][1] = Bc[b0 + 4];
            }
#pragma unroll
            for (int mt = 0; mt < 2; mt++)
#pragma unroll
                for (int nt = 0; nt < 8; nt++)
                    mma_f16(acc[mt][nt], af[mt], bf[nt]);
        }
    }

    const float* bias = biasEx ? biasEx
                      : (biasOff != NOBIAS ? (const float*)g_scratch + biasOff
                                           : nullptr);
    if (bias) bias += (size_t)z * biasStride;
#pragma unroll
    for (int mt = 0; mt < 2; mt++)
#pragma unroll
        for (int nt = 0; nt < 8; nt++)
#pragma unroll
            for (int hf = 0; hf < 2; hf++) {
                const int m = m0 + mBase + mt * 16 + gi + hf * 8;
                const int n = n0 + nBase + nt * 8 + 2 * gj;
                float v0 = acc[mt][nt][hf * 2 + 0];
                float v1 = acc[mt][nt][hf * 2 + 1];
                if (bias) { v0 += bias[n]; v1 += bias[n + 1]; }
                if constexpr (EPI == EPI_GELU) {
                    v0 = 0.5f * v0 * (1.f + erff(v0 * 0.70710678118654752f));
                    v1 = 0.5f * v1 * (1.f + erff(v1 * 0.70710678118654752f));
                }
                if constexpr (EPI == EPI_NONE) {
                    float* Cf = g_scratch + cOff;
                    *reinterpret_cast<float2*>(&Cf[(size_t)m * Ntot + n]) =
                        make_float2(v0, v1);
                } else {
                    __half* Ch = reinterpret_cast<__half*>(g_scratch + cOff);
                    if constexpr (EPI == EPI_GELU) {
                        *reinterpret_cast<__half2*>(&Ch[(size_t)m * Ntot + n]) =
                            __floats2half2_rn(v0, v1);
                    } else if constexpr (EPI == EPI_QKV) {
                        const int bb = m >> 9, s = m & 511, h = n >> 6, d = n & 63;
                        if (z < 2) {
                            *reinterpret_cast<__half2*>(
                                &Ch[(size_t)z * cStride
                                    + ((size_t)(bb * kNH + h) * kS + s) * kDH + d]) =
                                __floats2half2_rn(v0, v1);
                        } else {   // V^T: [bh][d][s]
                            __half* Vt = Ch + 2 * cStride
                                       + ((size_t)(bb * kNH + h) * kDH + d) * kS + s;
                            Vt[0]  = __float2half_rn(v0);
                            Vt[kS] = __float2half_rn(v1);
                        }
                    } else {       // EPI_POS
                        const int h = n >> 6, d = n & 63;
                        *reinterpret_cast<__half2*>(
                            &Ch[(size_t)z * cStride
                                + ((size_t)h * (2 * kP) + m) * kDH + d]) =
                            __floats2half2_rn(v0, v1);
                    }
                }
            }
}

// ---------------------------------------------------------------------------
// Band GEMM fp16: diagonal 128x128 tiles, K=64. Strides in HALF units.
// ---------------------------------------------------------------------------
constexpr int BH_HW = 36;

__global__ __launch_bounds__(256, 2)
void band_gemm_h(size_t aOff, size_t bOff, size_t cOff,
                 size_t aStride, size_t bStride, size_t cStride)
{
    __shared__ __align__(16) uint32_t As[128 * BH_HW], Bs[128 * BH_HW];
    const int z = blockIdx.z;
    const __half* Ah = reinterpret_cast<const __half*>(g_scratch + aOff)
                     + (size_t)z * aStride;
    const __half* Bh = reinterpret_cast<const __half*>(g_scratch + bOff)
                     + (size_t)(z % kNH) * bStride;
    __half* Ch = reinterpret_cast<__half*>(g_scratch + cOff) + (size_t)z * cStride;

    const int m0 = blockIdx.y * 128;
    const int n0 = blockIdx.y * 128 + blockIdx.x * 128;
    const int tid = threadIdx.x, warp = tid >> 5, lane = tid & 31;
    const int wm = warp & 3, wn = warp >> 2;
    const int mBase = wm * 32, nBase = wn * 64;
    const int gi = lane >> 2, gj = lane & 3;
    const uint32_t sA = smem_u32(As), sB = smem_u32(Bs);

#pragma unroll
    for (int i = 0; i < 4; i++) {
        const int idx = tid + i * 256;
        const int row = idx >> 3, g = idx & 7;
        cp_async16(sA + (uint32_t)(row * BH_HW + g * 4) * 4,
                   Ah + (size_t)(m0 + row) * kDH + g * 8);
        cp_async16(sB + (uint32_t)(row * BH_HW + g * 4) * 4,
                   Bh + (size_t)(n0 + row) * kDH + g * 8);
    }
    cp_commit();
    cp_wait0();
    __syncthreads();

    float acc[2][8][4];
#pragma unroll
    for (int i = 0; i < 2; i++)
#pragma unroll
        for (int j = 0; j < 8; j++)
#pragma unroll
            for (int r = 0; r < 4; r++) acc[i][j][r] = 0.f;

#pragma unroll
    for (int ks = 0; ks < 4; ks++) {
        const int kk = ks * 8;
        uint32_t af[2][4];
#pragma unroll
        for (int mt = 0; mt < 2; mt++) {
            const int r0 = (mBase + mt * 16 + gi) * BH_HW + kk + gj;
            af[mt][0] = As[r0];
            af[mt][1] = As[r0 + 8 * BH_HW];
            af[mt][2] = As[r0 + 4];
            af[mt][3] = As[r0 + 8 * BH_HW + 4];
        }
        uint32_t bf[8][2];
#pragma unroll
        for (int nt = 0; nt < 8; nt++) {
            const int b0 = (nBase + nt * 8 + gi) * BH_HW + kk + gj;
            bf[nt][0] = Bs[b0];
            bf[nt][1] = Bs[b0 + 4];
        }
#pragma unroll
        for (int mt = 0; mt < 2; mt++)
#pragma unroll
            for (int nt = 0; nt < 8; nt++)
                mma_f16(acc[mt][nt], af[mt], bf[nt]);
    }
#pragma unroll
    for (int mt = 0; mt < 2; mt++)
#pragma unroll
        for (int nt = 0; nt < 8; nt++)
#pragma unroll
            for (int hf = 0; hf < 2; hf++) {
                const int m = m0 + mBase + mt * 16 + gi + hf * 8;
                const int n = n0 + nBase + nt * 8 + 2 * gj;
                *reinterpret_cast<__half2*>(&Ch[(size_t)m * (2 * kP) + n]) =
                    __floats2half2_rn(acc[mt][nt][hf * 2 + 0],
                                      acc[mt][nt][hf * 2 + 1]);
            }
}

// ---------------------------------------------------------------------------
// Flash attention fp16 (unchanged from R14; reads now-correct K / V^T).
// ---------------------------------------------------------------------------
constexpr int FH_QS = 0;
constexpr int FH_KS = 128 * 36;
constexpr int FH_VS = 2 * 128 * 36;
constexpr int FH_PG = FH_VS + 64 * 68;
constexpr int FA_SMEM = (FH_PG + 128 * 132) * 4;

__global__ __launch_bounds__(256, 1)
void flash_attn_kernel(const float* __restrict__ mask)
{
    extern __shared__ __align__(16) uint32_t fsm[];
    uint32_t* Qs = fsm + FH_QS;
    uint32_t* Ks = fsm + FH_KS;
    uint32_t* Vs = fsm + FH_VS;
    float*    Pg = reinterpret_cast<float*>(fsm + FH_PG);
    uint32_t* Pp = fsm + FH_PG;

    const int z  = blockIdx.y;
    const int i0 = blockIdx.x * 128;
    const int tid = threadIdx.x, warp = tid >> 5, lane = tid & 31;
    const int gi = lane >> 2, gj = lane & 3;
    const int mBase = warp * 16;

    const __half* Qh = reinterpret_cast<const __half*>(g_scratch + OFF_Q)
                     + (size_t)z * kS * kDH;
    const __half* Kh = reinterpret_cast<const __half*>(g_scratch + OFF_K)
                     + (size_t)z * kS * kDH;
    const __half* Vth = reinterpret_cast<const __half*>(g_scratch + OFF_V)
                      + (size_t)z * kDH * kS;
    const __half* C2Ph = reinterpret_cast<const __half*>(g_scratch + OFF_C2P)
                       + (size_t)z * kS * (2 * kP);
    const __half* P2Ch = reinterpret_cast<const __half*>(g_scratch + OFF_P2C)
                       + (size_t)z * kS * (2 * kP);
    const float* mrow = mask + (size_t)(z / kNH) * kS;

#pragma unroll
    for (int r = 0; r < 4; r++) {
        const int idx = tid + r * 256;
        const int row = idx >> 3, g = idx & 7;
        *reinterpret_cast<uint4*>(&Qs[row * 36 + g * 4]) =
            *reinterpret_cast<const uint4*>(Qh + (size_t)(i0 + row) * kDH + g * 8);
    }

    float ctx[8][4];
#pragma unroll
    for (int n = 0; n < 8; n++)
#pragma unroll
        for (int c = 0; c < 4; c++) ctx[n][c] = 0.f;
    float rm[2] = {-1e30f, -1e30f};
    float rs[2] = {0.f, 0.f};

    for (int jt = 0; jt < 4; jt++) {
        const int j0 = jt * 128;
        __syncthreads();
#pragma unroll
        for (int r = 0; r < 4; r++) {
            const int idx = tid + r * 256;
            const int row = idx >> 3, g = idx & 7;
            *reinterpret_cast<uint4*>(&Ks[row * 36 + g * 4]) =
                *reinterpret_cast<const uint4*>(Kh + (size_t)(j0 + row) * kDH + g * 8);
        }
#pragma unroll
        for (int r = 0; r < 4; r++) {
            const int idx = tid + r * 256;
            const int row = idx >> 4, g = idx & 15;
            *reinterpret_cast<uint4*>(&Vs[row * 68 + g * 4]) =
                *reinterpret_cast<const uint4*>(Vth + (size_t)row * kS + j0 + g * 8);
        }
        __syncthreads();

        float accS[16][4];
#pragma unroll
        for (int n = 0; n < 16; n++)
#pragma unroll
            for (int c = 0; c < 4; c++) accS[n][c] = 0.f;
#pragma unroll
        for (int ks = 0; ks < 4; ks++) {
            const int kk = ks * 8;
            uint32_t af[4];
            const int r0 = (mBase + gi) * 36 + kk + gj;
            af[0] = Qs[r0];
            af[1] = Qs[r0 + 8 * 36];
            af[2] = Qs[r0 + 4];
            af[3] = Qs[r0 + 8 * 36 + 4];
#pragma unroll
            for (int nt = 0; nt < 16; nt++) {
                uint32_t bf[2];
                const int b0 = (nt * 8 + gi) * 36 + kk + gj;
                bf[0] = Ks[b0];
                bf[1] = Ks[b0 + 4];
                mma_f16(accS[nt], af, bf);
            }
        }

#pragma unroll
        for (int r = 0; r < 64; r++) {
            const int idx = tid + r * 256;
            const int jl = idx >> 7, il = idx & 127;
            Pg[jl * 132 + il] = __half2float(
                P2Ch[(size_t)(j0 + jl) * (2 * kP) + (j0 + jl) - (i0 + il) + kP]);
        }
        __syncthreads();
#pragma unroll
        for (int nt = 0; nt < 16; nt++)
#pragma unroll
            for (int hf = 0; hf < 2; hf++) {
                const int il = mBase + gi + hf * 8;
                const int jl = nt * 8 + 2 * gj;
                accS[nt][hf * 2 + 0] += Pg[jl * 132 + il];
                accS[nt][hf * 2 + 1] += Pg[(jl + 1) * 132 + il];
            }
        __syncthreads();
#pragma unroll
        for (int r = 0; r < 64; r++) {
            const int idx = tid + r * 256;
            const int il = idx >> 7, jl = idx & 127;
            Pg[il * 132 + jl] = __half2float(
                C2Ph[(size_t)(i0 + il) * (2 * kP) + (i0 + il) - (j0 + jl) + kP]);
        }
        __syncthreads();
#pragma unroll
        for (int nt = 0; nt < 16; nt++)
#pragma unroll
            for (int hf = 0; hf < 2; hf++) {
                const int il = mBase + gi + hf * 8;
                const int jl = nt * 8 + 2 * gj;
                float s0 = (accS[nt][hf * 2 + 0] + Pg[il * 132 + jl]) * kScale;
                float s1 = (accS[nt][hf * 2 + 1] + Pg[il * 132 + jl + 1]) * kScale;
                if (mrow[j0 + jl] <= 0.f)     s0 = -1e9f;
                if (mrow[j0 + jl + 1] <= 0.f) s1 = -1e9f;
                accS[nt][hf * 2 + 0] = s0;
                accS[nt][hf * 2 + 1] = s1;
            }

#pragma unroll
        for (int hf = 0; hf < 2; hf++) {
            float tmax = -1e30f;
#pragma unroll
            for (int nt = 0; nt < 16; nt++)
                tmax = fmaxf(tmax, fmaxf(accS[nt][hf * 2], accS[nt][hf * 2 + 1]));
            tmax = fmaxf(tmax, __shfl_xor_sync(0xFFFFFFFFu, tmax, 1));
            tmax = fmaxf(tmax, __shfl_xor_sync(0xFFFFFFFFu, tmax, 2));
            const float mNew = fmaxf(rm[hf], tmax);
            const float alpha = __expf(rm[hf] - mNew);
            float lsum = 0.f;
#pragma unroll
            for (int nt = 0; nt < 16; nt++) {
                const float e0 = __expf(accS[nt][hf * 2 + 0] - mNew);
                const float e1 = __expf(accS[nt][hf * 2 + 1] - mNew);
                accS[nt][hf * 2 + 0] = e0;
                accS[nt][hf * 2 + 1] = e1;
                lsum += e0 + e1;
            }
            lsum += __shfl_xor_sync(0xFFFFFFFFu, lsum, 1);
            lsum += __shfl_xor_sync(0xFFFFFFFFu, lsum, 2);
            rs[hf] = rs[hf] * alpha + lsum;
            rm[hf] = mNew;
#pragma unroll
            for (int n = 0; n < 8; n++) {
                ctx[n][hf * 2 + 0] *= alpha;
                ctx[n][hf * 2 + 1] *= alpha;
            }
        }

        __syncthreads();
#pragma unroll
        for (int nt = 0; nt < 16; nt++)
#pragma unroll
            for (int hf = 0; hf < 2; hf++) {
                const int il = mBase + gi + hf * 8;
                const __half2 p = __floats2half2_rn(accS[nt][hf * 2 + 0],
                                                    accS[nt][hf * 2 + 1]);
                Pp[il * 68 + nt * 4 + gj] = *reinterpret_cast<const uint32_t*>(&p);
            }
        __syncthreads();

#pragma unroll
        for (int ks = 0; ks < 8; ks++) {
            const int kk = ks * 8;
            uint32_t af[4];
            const int r0 = (mBase + gi) * 68 + kk + gj;
            af[0] = Pp[r0];
            af[1] = Pp[r0 + 8 * 68];
            af[2] = Pp[r0 + 4];
            af[3] = Pp[r0 + 8 * 68 + 4];
#pragma unroll
            for (int nt = 0; nt < 8; nt++) {
                uint32_t bf[2];
                const int b0 = (nt * 8 + gi) * 68 + kk + gj;
                bf[0] = Vs[b0];
                bf[1] = Vs[b0 + 4];
                mma_f16(ctx[nt], af, bf);
            }
        }
    }

    const int bb = z / kNH, h = z % kNH;
    const float inv0 = 1.f / rs[0], inv1 = 1.f / rs[1];
    __half* Cg = reinterpret_cast<__half*>(g_scratch + OFF_CTX);
#pragma unroll
    for (int nt = 0; nt < 8; nt++)
#pragma unroll
        for (int hf = 0; hf < 2; hf++) {
            const int m = i0 + mBase + gi + hf * 8;
            const int d = nt * 8 + 2 * gj;
            const float inv = hf ? inv1 : inv0;
            *reinterpret_cast<__half2*>(
                &Cg[((size_t)bb * kS + m) * kH + h * kDH + d]) =
                __floats2half2_rn(ctx[nt][hf * 2 + 0] * inv,
                                  ctx[nt][hf * 2 + 1] * inv);
        }
}

// ---------------------------------------------------------------------------
// out = LayerNorm(X + Y) * g + b; optional half copy for next GEMM.
// ---------------------------------------------------------------------------
__global__ void add_ln_kernel(const float* __restrict__ Xex, size_t xOff, size_t yOff,
                              const float* __restrict__ g, const float* __restrict__ bb,
                              float* __restrict__ outEx, size_t outOff,
                              int makeHalf, size_t rOff)
{
    const float* X = Xex ? Xex : (const float*)g_scratch + xOff;
    const float* Y = (const float*)g_scratch + yOff;
    float* O = outEx ? outEx : g_scratch + outOff;

    const size_t off = (size_t)blockIdx.x * kH;
    const int t = threadIdx.x;
    const float v0 = X[off + t]       + Y[off + t];
    const float v1 = X[off + t + 256] + Y[off + t + 256];
    const float v2 = X[off + t + 512] + Y[off + t + 512];

    __shared__ float red[256];
    red[t] = v0 + v1 + v2;
    __syncthreads();
    for (int s = 128; s > 0; s >>= 1) {
        if (t < s) red[t] += red[t + s];
        __syncthreads();
    }
    const float mean = red[0] * (1.f / 768.f);
    __syncthreads();
    const float d0 = v0 - mean, d1 = v1 - mean, d2 = v2 - mean;
    red[t] = d0 * d0 + d1 * d1 + d2 * d2;
    __syncthreads();
    for (int s = 128; s > 0; s >>= 1) {
        if (t < s) red[t] += red[t + s];
        __syncthreads();
    }
    const float rstd = rsqrtf(red[0] * (1.f / 768.f) + 1e-7f);

    const float o0 = d0 * rstd * g[t]       + bb[t];
    const float o1 = d1 * rstd * g[t + 256] + bb[t + 256];
    const float o2 = d2 * rstd * g[t + 512] + bb[t + 512];
    O[off + t]       = o0;
    O[off + t + 256] = o1;
    O[off + t + 512] = o2;
    if (makeHalf) {
        __half* R = reinterpret_cast<__half*>(g_scratch + rOff);
        R[off + t]       = __float2half_rn(o0);
        R[off + t + 256] = __float2half_rn(o1);
        R[off + t + 512] = __float2half_rn(o2);
    }
}

// ---------------------------------------------------------------------------
extern "C" void kernel_launch(void* const* d_in, const int* in_sizes, int n_in,
                              void* d_out, int out_size)
{
    const float* hs  = (const float*)d_in[0];
    const float* am  = (const float*)d_in[1];
    const float* pe  = (const float*)d_in[2];
    const float* Wq  = (const float*)d_in[3];
    const float* bq  = (const float*)d_in[4];
    const float* Wk  = (const float*)d_in[5];
    const float* bk  = (const float*)d_in[6];
    const float* Wv  = (const float*)d_in[7];
    const float* bv  = (const float*)d_in[8];
    const float* Wpk = (const float*)d_in[9];
    const float* Wpq = (const float*)d_in[10];
    const float* Wo  = (const float*)d_in[11];
    const float* bo  = (const float*)d_in[12];
    const float* g1  = (const float*)d_in[13];
    const float* be1 = (const float*)d_in[14];
    const float* W1  = (const float*)d_in[15];
    const float* b1  = (const float*)d_in[16];
    const float* W2  = (const float*)d_in[17];
    const float* b2  = (const float*)d_in[18];
    const float* g2  = (const float*)d_in[19];
    const float* be2 = (const float*)d_in[20];
    float* out = (float*)d_out;

    auto qkvK = gemm_h<EPI_QKV>;
    auto posK = gemm_h<EPI_POS>;
    auto nnK  = gemm_h<EPI_NONE>;
    auto gelK = gemm_h<EPI_GELU>;
    cudaFuncSetAttribute((const void*)qkvK, cudaFuncAttributeMaxDynamicSharedMemorySize, GH_SMEM);
    cudaFuncSetAttribute((const void*)posK, cudaFuncAttributeMaxDynamicSharedMemorySize, GH_SMEM);
    cudaFuncSetAttribute((const void*)nnK,  cudaFuncAttributeMaxDynamicSharedMemorySize, GH_SMEM);
    cudaFuncSetAttribute((const void*)gelK, cudaFuncAttributeMaxDynamicSharedMemorySize, GH_SMEM);
    cudaFuncSetAttribute((const void*)flash_attn_kernel,
                         cudaFuncAttributeMaxDynamicSharedMemorySize, FA_SMEM);

    preconvert_kernel<<<(int)((F4_TOTAL + 255) / 256), 256>>>(hs, pe, bq, bk, bv);
    transpose_kernel<<<8064, 256>>>(Wq, Wk, Wv, Wpk, Wpq, Wo, W1, W2);

    // QKV: z region strides in HALF units (2*SZ_W weights, 2*SZ_QKV outputs)
    qkvK<<<dim3(kH / 128, kBS / 128, 3), 256, GH_SMEM>>>(
        OFF_CHS, OFF_CWQ, 2 * SZ_W, nullptr, OFF_CB, kH, OFF_Q, 2 * SZ_QKV, kH, kH);
    // pos projections: HALF-unit strides
    posK<<<dim3(kH / 128, (2 * kP) / 128, 2), 256, GH_SMEM>>>(
        OFF_CPE, OFF_CWPK, 2 * SZ_W, nullptr, NOBIAS, 0, OFF_PK, 2 * SZ_POS, kH, kH);

    // band GEMMs (diagonal tiles, fp16 out; strides already HALF units)
    band_gemm_h<<<dim3(5, kS / 128, kBH), 256>>>(
        OFF_Q, OFF_PK, OFF_C2P,
        (size_t)kS * kDH, (size_t)(2 * kP) * kDH, (size_t)kS * (2 * kP));
    band_gemm_h<<<dim3(5, kS / 128, kBH), 256>>>(
        OFF_K, OFF_PQ, OFF_P2C,
        (size_t)kS * kDH, (size_t)(2 * kP) * kDH, (size_t)kS * (2 * kP));

    // fused flash attention -> CTX (half)
    flash_attn_kernel<<<dim3(kS / 128, kBH), 256, FA_SMEM>>>(am);

    // Wo + LN1
    nnK<<<dim3(kH / 128, kBS / 128, 1), 256, GH_SMEM>>>(
        OFF_CTX, OFF_CWO, 0, bo, NOBIAS, 0, OFF_T1, 0, kH, kH);
    add_ln_kernel<<<kBS, 256>>>(hs, 0, OFF_T1, g1, be1, nullptr, OFF_H1, 1, OFF_H1R);

    // FFN
    gelK<<<dim3(kI / 128, kBS / 128, 1), 256, GH_SMEM>>>(
        OFF_H1R, OFF_CW1, 0, b1, NOBIAS, 0, OFF_F1, 0, kH, kI);
    nnK<<<dim3(kH / 128, kBS / 128, 1), 256, GH_SMEM>>>(
        OFF_F1, OFF_CW2, 0, b2, NOBIAS, 0, OFF_T1, 0, kI, kH);
    add_ln_kernel<<<kBS, 256>>>(nullptr, OFF_H1, OFF_T1, g2, be2, out, 0, 0, 0);
}